// round 7
// baseline (speedup 1.0000x reference)
#include <cuda_runtime.h>
#include <math.h>

#define Bsz 16
#define Ssz 2048
#define Dsz 256
#define LAM (0.02f / 4096.0f)   // 0.01 * 2/(B*D)

// Scratch (device globals: allocation-free per harness rules)
__device__ float g_state[Ssz * Bsz * Dsz];   // [s][b][k]  = tanh(alpha1*x)
__device__ float g_train[Ssz * Bsz * Dsz];   // [s][b][k]  = state + noise
__device__ float g_M[Ssz * Bsz * Bsz];       // [s][b][b'] = sum_k state[b,k]*train[b',k]
__device__ float g_v[Bsz * Ssz * Dsz];       // [b][s][k]  = tanh(alpha2*x)

// ---------------------------------------------------------------------------
// prep: elementwise tanh/add, produce state, train (transposed to [s][b][k]) and v
// ---------------------------------------------------------------------------
__global__ void prep_kernel(const float* __restrict__ x, const float* __restrict__ noise,
                            const float* __restrict__ a1, const float* __restrict__ a2) {
    int idx4 = blockIdx.x * blockDim.x + threadIdx.x;     // over B*S*D/4 float4s
    int base = idx4 * 4;
    int k  = base & (Dsz - 1);
    int bs = base >> 8;              // b*S + s
    int b  = bs >> 11;               // /2048
    int s  = bs & (Ssz - 1);

    float4 xv = ((const float4*)x)[idx4];
    float4 nv = ((const float4*)noise)[idx4];
    float4 A1 = ((const float4*)a1)[k >> 2];
    float4 A2 = ((const float4*)a2)[k >> 2];

    float4 st, tr, vv;
    st.x = tanhf(A1.x * xv.x);  st.y = tanhf(A1.y * xv.y);
    st.z = tanhf(A1.z * xv.z);  st.w = tanhf(A1.w * xv.w);
    tr.x = st.x + nv.x; tr.y = st.y + nv.y; tr.z = st.z + nv.z; tr.w = st.w + nv.w;
    vv.x = tanhf(A2.x * xv.x);  vv.y = tanhf(A2.y * xv.y);
    vv.z = tanhf(A2.z * xv.z);  vv.w = tanhf(A2.w * xv.w);

    int o = (s * Bsz + b) * Dsz + k;
    *(float4*)&g_state[o] = st;
    *(float4*)&g_train[o] = tr;
    ((float4*)g_v)[idx4] = vv;
}

// ---------------------------------------------------------------------------
// prep_M: M[s][b][b'] = sum_k state[s][b][k] * train[s][b'][k]
// ---------------------------------------------------------------------------
__global__ void prep_M_kernel() {
    __shared__ float sst[Bsz][Dsz + 4];
    __shared__ float str_[Bsz][Dsz + 4];
    int s = blockIdx.x;
    const float* sp = g_state + s * (Bsz * Dsz);
    const float* tp = g_train + s * (Bsz * Dsz);

    for (int i = threadIdx.x; i < Bsz * Dsz / 4; i += 256) {
        int b = (i * 4) / Dsz;
        int k = (i * 4) % Dsz;
        *(float4*)&sst[b][k]  = *(const float4*)&sp[b * Dsz + k];
        *(float4*)&str_[b][k] = *(const float4*)&tp[b * Dsz + k];
    }
    __syncthreads();

    int b  = threadIdx.x >> 4;
    int bp = threadIdx.x & 15;
    float acc = 0.0f;
#pragma unroll 8
    for (int k = 0; k < Dsz; k += 4) {
        float4 a = *(float4*)&sst[b][k];
        float4 c = *(float4*)&str_[bp][k];
        acc += a.x * c.x + a.y * c.y + a.z * c.z + a.w * c.w;
    }
    g_M[(s * Bsz + b) * Bsz + bp] = acc;
}

// ---------------------------------------------------------------------------
// ff: out[row][j] = u(row,j) * sum_k v[row][k] * Wp[j][k]
// Tiled fp32 GEMM: BM=64, BN=64, BK=16, 256 threads, 4x4 per thread.
// ---------------------------------------------------------------------------
__global__ void ff_kernel(const float* __restrict__ Wp,
                          const float* __restrict__ ffa, const float* __restrict__ ffb,
                          const float* __restrict__ ffg, const float* __restrict__ ffe,
                          float* __restrict__ out) {
    __shared__ float As[16][68];
    __shared__ float Bs[16][68];

    int rowTile = blockIdx.x * 64;
    int jTile   = blockIdx.y * 64;
    int tid = threadIdx.x;
    int tx = tid & 15;          // col group
    int ty = tid >> 4;          // row group

    float acc[4][4];
#pragma unroll
    for (int i = 0; i < 4; i++)
#pragma unroll
        for (int j = 0; j < 4; j++) acc[i][j] = 0.0f;

    int r  = tid >> 2;          // 0..63
    int kk = (tid & 3) * 4;     // 0,4,8,12

    for (int kt = 0; kt < Dsz; kt += 16) {
        float4 av = *(const float4*)&g_v[(size_t)(rowTile + r) * Dsz + kt + kk];
        float4 bv = *(const float4*)&Wp[(jTile + r) * Dsz + kt + kk];
        As[kk + 0][r] = av.x; As[kk + 1][r] = av.y; As[kk + 2][r] = av.z; As[kk + 3][r] = av.w;
        Bs[kk + 0][r] = bv.x; Bs[kk + 1][r] = bv.y; Bs[kk + 2][r] = bv.z; Bs[kk + 3][r] = bv.w;
        __syncthreads();
#pragma unroll
        for (int k2 = 0; k2 < 16; k2++) {
            float4 a = *(float4*)&As[k2][ty * 4];
            float4 b = *(float4*)&Bs[k2][tx * 4];
            acc[0][0] += a.x * b.x; acc[0][1] += a.x * b.y; acc[0][2] += a.x * b.z; acc[0][3] += a.x * b.w;
            acc[1][0] += a.y * b.x; acc[1][1] += a.y * b.y; acc[1][2] += a.y * b.z; acc[1][3] += a.y * b.w;
            acc[2][0] += a.z * b.x; acc[2][1] += a.z * b.y; acc[2][2] += a.z * b.z; acc[2][3] += a.z * b.w;
            acc[3][0] += a.w * b.x; acc[3][1] += a.w * b.y; acc[3][2] += a.w * b.z; acc[3][3] += a.w * b.w;
        }
        __syncthreads();
    }

    float gg = ffg[0];
    float ee = ffe[0];
#pragma unroll
    for (int i = 0; i < 4; i++) {
        int row = rowTile + ty * 4 + i;
#pragma unroll
        for (int j = 0; j < 4; j++) {
            int col = jTile + tx * 4 + j;
            float vv = g_v[(size_t)row * Dsz + col];
            float za = ffa[col] * vv;
            float gel = 0.5f * za * (1.0f + erff(za * 0.70710678118654752f));
            float u = gg * gel + ee * sinf(ffb[col] * vv);
            out[(size_t)row * Dsz + col] = u * acc[i][j];
        }
    }
}

// ---------------------------------------------------------------------------
// ttt: 256 independent per-row recurrences. One warp per row (128 blocks x 2 warps).
// Lane t owns w[k] for k in {4t..4t+3} and {128+4t..128+4t+3} (two float4 granules).
// ---------------------------------------------------------------------------
__global__ void __launch_bounds__(64) ttt_kernel(const float* __restrict__ Wt,
                                                 float* __restrict__ out) {
    __shared__ float red[2][32][36];

    int warp = threadIdx.x >> 5;
    int lane = threadIdx.x & 31;
    int d1 = blockIdx.x * 2 + warp;
    int bsel = lane & 15;

    float4 w0 = *(const float4*)&Wt[d1 * Dsz + 4 * lane];
    float4 w1 = *(const float4*)&Wt[d1 * Dsz + 128 + 4 * lane];

    float (*rd)[36] = red[warp];

    for (int s = 0; s < Ssz; s++) {
        __syncthreads();   // keep the two warps in step for L1 locality

        const float* tr = g_train + (size_t)s * (Bsz * Dsz);
        const float* st = g_state + (size_t)s * (Bsz * Dsz);

        // Phase 1: partial dots  pp[b] = train[b,:]·w  (my k-slice),  qq[b] = state[b,:]·w
        float pp[16], qq[16];
#pragma unroll 4
        for (int b = 0; b < 16; b++) {
            float4 ta = *(const float4*)&tr[b * Dsz + 4 * lane];
            float4 tb = *(const float4*)&tr[b * Dsz + 128 + 4 * lane];
            float4 sa = *(const float4*)&st[b * Dsz + 4 * lane];
            float4 sb = *(const float4*)&st[b * Dsz + 128 + 4 * lane];
            pp[b] = ta.x * w0.x + ta.y * w0.y + ta.z * w0.z + ta.w * w0.w
                  + tb.x * w1.x + tb.y * w1.y + tb.z * w1.z + tb.w * w1.w;
            qq[b] = sa.x * w0.x + sa.y * w0.y + sa.z * w0.z + sa.w * w0.w
                  + sb.x * w1.x + sb.y * w1.y + sb.z * w1.z + sb.w * w1.w;
        }

        // Reduce 32 sums across 32 lanes via smem transpose:
        // result: lane b -> p[b], lane 16+b -> q[b]
#pragma unroll
        for (int i = 0; i < 16; i++) {
            rd[i][lane] = pp[i];
            rd[16 + i][lane] = qq[i];
        }
        __syncwarp();
        float4 v0 = *(float4*)&rd[lane][0];
        float4 v1 = *(float4*)&rd[lane][4];
        float4 v2 = *(float4*)&rd[lane][8];
        float4 v3 = *(float4*)&rd[lane][12];
        float4 v4 = *(float4*)&rd[lane][16];
        float4 v5 = *(float4*)&rd[lane][20];
        float4 v6 = *(float4*)&rd[lane][24];
        float4 v7 = *(float4*)&rd[lane][28];
        float4 sA = make_float4(v0.x + v1.x, v0.y + v1.y, v0.z + v1.z, v0.w + v1.w);
        float4 sB = make_float4(v2.x + v3.x, v2.y + v3.y, v2.z + v3.z, v2.w + v3.w);
        float4 sC = make_float4(v4.x + v5.x, v4.y + v5.y, v4.z + v5.z, v4.w + v5.w);
        float4 sD = make_float4(v6.x + v7.x, v6.y + v7.y, v6.z + v7.z, v6.w + v7.w);
        float4 sE = make_float4(sA.x + sB.x, sA.y + sB.y, sA.z + sB.z, sA.w + sB.w);
        float4 sF = make_float4(sC.x + sD.x, sC.y + sD.y, sC.z + sD.z, sC.w + sD.w);
        float tot = (sE.x + sF.x) + (sE.y + sF.y) + (sE.z + sF.z) + (sE.w + sF.w);
        __syncwarp();

        // diff[b] = p[b] - state[b][d1]   (meaningful on lanes < 16)
        float scold = st[bsel * Dsz + d1];
        float diffv = tot - scold;

        float dif[16];
#pragma unroll
        for (int j = 0; j < 16; j++) dif[j] = __shfl_sync(0xffffffffu, diffv, j);

        // Readout: out[b] = q[b] - lam * sum_j M[b][j]*dif[j]   (lanes >= 16, b = bsel)
        const float* Mrow = g_M + (size_t)(s * Bsz + bsel) * Bsz;
        float4 m0 = *(const float4*)&Mrow[0];
        float4 m1 = *(const float4*)&Mrow[4];
        float4 m2 = *(const float4*)&Mrow[8];
        float4 m3 = *(const float4*)&Mrow[12];
        float corr = m0.x * dif[0] + m0.y * dif[1] + m0.z * dif[2] + m0.w * dif[3]
                   + m1.x * dif[4] + m1.y * dif[5] + m1.z * dif[6] + m1.w * dif[7]
                   + m2.x * dif[8] + m2.y * dif[9] + m2.z * dif[10] + m2.w * dif[11]
                   + m3.x * dif[12] + m3.y * dif[13] + m3.z * dif[14] + m3.w * dif[15];
        float oacc = tot - LAM * corr;
        if (lane >= 16) {
            float* op = out + ((size_t)bsel * Ssz + s) * Dsz + d1;
            *op += oacc;    // ff kernel wrote g first
        }

        // Update w:  w[k] -= lam * sum_b dif[b] * train[b,k]
#pragma unroll 4
        for (int b = 0; b < 16; b++) {
            float4 ta = *(const float4*)&tr[b * Dsz + 4 * lane];
            float4 tb = *(const float4*)&tr[b * Dsz + 128 + 4 * lane];
            float ld = LAM * dif[b];
            w0.x -= ld * ta.x; w0.y -= ld * ta.y; w0.z -= ld * ta.z; w0.w -= ld * ta.w;
            w1.x -= ld * tb.x; w1.y -= ld * tb.y; w1.z -= ld * tb.z; w1.w -= ld * tb.w;
        }
    }
}

// ---------------------------------------------------------------------------
extern "C" void kernel_launch(void* const* d_in, const int* in_sizes, int n_in,
                              void* d_out, int out_size) {
    const float* x     = (const float*)d_in[0];
    const float* noise = (const float*)d_in[1];
    const float* a1    = (const float*)d_in[2];
    const float* a2    = (const float*)d_in[3];
    const float* Wt    = (const float*)d_in[4];
    const float* Wp    = (const float*)d_in[5];
    const float* ffa   = (const float*)d_in[6];
    const float* ffb   = (const float*)d_in[7];
    const float* ffg   = (const float*)d_in[8];
    const float* ffe   = (const float*)d_in[9];
    float* out = (float*)d_out;

    prep_kernel<<<(Bsz * Ssz * Dsz / 4) / 256, 256>>>(x, noise, a1, a2);
    prep_M_kernel<<<Ssz, 256>>>();
    ff_kernel<<<dim3((Bsz * Ssz) / 64, Dsz / 64), 256>>>(Wp, ffa, ffb, ffg, ffe, out);
    ttt_kernel<<<Dsz / 2, 64>>>(Wt, out);
}

// round 9
// speedup vs baseline: 5.0666x; 5.0666x over previous
#include <cuda_runtime.h>
#include <cuda_pipeline.h>
#include <math.h>

#define Bsz 16
#define Ssz 2048
#define Dsz 256
#define LAM (0.02f / 4096.0f)   // 0.01 * 2/(B*D)
#define TSTR 260                // smem tile row stride (floats), padded

// Scratch (device globals: allocation-free per harness rules)
__device__ float g_state[Ssz * Bsz * Dsz];   // [s][b][k]  = tanh(alpha1*x)
__device__ float g_train[Ssz * Bsz * Dsz];   // [s][b][k]  = state + noise
__device__ float g_M[Ssz * Bsz * Bsz];       // [s][b][b'] = sum_k state[b,k]*train[b',k]
__device__ float g_v[Bsz * Ssz * Dsz];       // [b][s][k]  = tanh(alpha2*x)

// ---------------------------------------------------------------------------
// prep: elementwise tanh/add, produce state, train (transposed to [s][b][k]) and v
// ---------------------------------------------------------------------------
__global__ void prep_kernel(const float* __restrict__ x, const float* __restrict__ noise,
                            const float* __restrict__ a1, const float* __restrict__ a2) {
    int idx4 = blockIdx.x * blockDim.x + threadIdx.x;     // over B*S*D/4 float4s
    int base = idx4 * 4;
    int k  = base & (Dsz - 1);
    int bs = base >> 8;              // b*S + s
    int b  = bs >> 11;               // /2048
    int s  = bs & (Ssz - 1);

    float4 xv = ((const float4*)x)[idx4];
    float4 nv = ((const float4*)noise)[idx4];
    float4 A1 = ((const float4*)a1)[k >> 2];
    float4 A2 = ((const float4*)a2)[k >> 2];

    float4 st, tr, vv;
    st.x = tanhf(A1.x * xv.x);  st.y = tanhf(A1.y * xv.y);
    st.z = tanhf(A1.z * xv.z);  st.w = tanhf(A1.w * xv.w);
    tr.x = st.x + nv.x; tr.y = st.y + nv.y; tr.z = st.z + nv.z; tr.w = st.w + nv.w;
    vv.x = tanhf(A2.x * xv.x);  vv.y = tanhf(A2.y * xv.y);
    vv.z = tanhf(A2.z * xv.z);  vv.w = tanhf(A2.w * xv.w);

    int o = (s * Bsz + b) * Dsz + k;
    *(float4*)&g_state[o] = st;
    *(float4*)&g_train[o] = tr;
    ((float4*)g_v)[idx4] = vv;
}

// ---------------------------------------------------------------------------
// prep_M: M[s][b][b'] = sum_k state[s][b][k] * train[s][b'][k]
// ---------------------------------------------------------------------------
__global__ void prep_M_kernel() {
    __shared__ float sst[Bsz][Dsz + 4];
    __shared__ float str_[Bsz][Dsz + 4];
    int s = blockIdx.x;
    const float* sp = g_state + s * (Bsz * Dsz);
    const float* tp = g_train + s * (Bsz * Dsz);

    for (int i = threadIdx.x; i < Bsz * Dsz / 4; i += 256) {
        int b = (i * 4) / Dsz;
        int k = (i * 4) % Dsz;
        *(float4*)&sst[b][k]  = *(const float4*)&sp[b * Dsz + k];
        *(float4*)&str_[b][k] = *(const float4*)&tp[b * Dsz + k];
    }
    __syncthreads();

    int b  = threadIdx.x >> 4;
    int bp = threadIdx.x & 15;
    float acc = 0.0f;
#pragma unroll 8
    for (int k = 0; k < Dsz; k += 4) {
        float4 a = *(float4*)&sst[b][k];
        float4 c = *(float4*)&str_[bp][k];
        acc += a.x * c.x + a.y * c.y + a.z * c.z + a.w * c.w;
    }
    g_M[(s * Bsz + b) * Bsz + bp] = acc;
}

// ---------------------------------------------------------------------------
// ff: out[row][j] = u(row,j) * sum_k v[row][k] * Wp[j][k]
// Tiled fp32 GEMM: BM=64, BN=64, BK=16, 256 threads, 4x4 per thread.
// ---------------------------------------------------------------------------
__global__ void ff_kernel(const float* __restrict__ Wp,
                          const float* __restrict__ ffa, const float* __restrict__ ffb,
                          const float* __restrict__ ffg, const float* __restrict__ ffe,
                          float* __restrict__ out) {
    __shared__ float As[16][68];
    __shared__ float Bs[16][68];

    int rowTile = blockIdx.x * 64;
    int jTile   = blockIdx.y * 64;
    int tid = threadIdx.x;
    int tx = tid & 15;          // col group
    int ty = tid >> 4;          // row group

    float acc[4][4];
#pragma unroll
    for (int i = 0; i < 4; i++)
#pragma unroll
        for (int j = 0; j < 4; j++) acc[i][j] = 0.0f;

    int r  = tid >> 2;          // 0..63
    int kk = (tid & 3) * 4;     // 0,4,8,12

    for (int kt = 0; kt < Dsz; kt += 16) {
        float4 av = *(const float4*)&g_v[(size_t)(rowTile + r) * Dsz + kt + kk];
        float4 bv = *(const float4*)&Wp[(jTile + r) * Dsz + kt + kk];
        As[kk + 0][r] = av.x; As[kk + 1][r] = av.y; As[kk + 2][r] = av.z; As[kk + 3][r] = av.w;
        Bs[kk + 0][r] = bv.x; Bs[kk + 1][r] = bv.y; Bs[kk + 2][r] = bv.z; Bs[kk + 3][r] = bv.w;
        __syncthreads();
#pragma unroll
        for (int k2 = 0; k2 < 16; k2++) {
            float4 a = *(float4*)&As[k2][ty * 4];
            float4 b = *(float4*)&Bs[k2][tx * 4];
            acc[0][0] += a.x * b.x; acc[0][1] += a.x * b.y; acc[0][2] += a.x * b.z; acc[0][3] += a.x * b.w;
            acc[1][0] += a.y * b.x; acc[1][1] += a.y * b.y; acc[1][2] += a.y * b.z; acc[1][3] += a.y * b.w;
            acc[2][0] += a.z * b.x; acc[2][1] += a.z * b.y; acc[2][2] += a.z * b.z; acc[2][3] += a.z * b.w;
            acc[3][0] += a.w * b.x; acc[3][1] += a.w * b.y; acc[3][2] += a.w * b.z; acc[3][3] += a.w * b.w;
        }
        __syncthreads();
    }

    float gg = ffg[0];
    float ee = ffe[0];
#pragma unroll
    for (int i = 0; i < 4; i++) {
        int row = rowTile + ty * 4 + i;
#pragma unroll
        for (int j = 0; j < 4; j++) {
            int col = jTile + tx * 4 + j;
            float vv = g_v[(size_t)row * Dsz + col];
            float za = ffa[col] * vv;
            float gel = 0.5f * za * (1.0f + erff(za * 0.70710678118654752f));
            float u = gg * gel + ee * sinf(ffb[col] * vv);
            out[(size_t)row * Dsz + col] = u * acc[i][j];
        }
    }
}

// ---------------------------------------------------------------------------
// ttt: 256 rows, 128 blocks x 256 threads. 2 rows per block, 4 warps per row.
// Lane owns 2 consecutive k's of w. Tiles double-buffered in smem via cp.async.
// Cross-lane reduction is a register-only shuffle butterfly (no smem traffic).
// ---------------------------------------------------------------------------
__device__ __forceinline__ void stage_tile(int s, float* trb, float* stb, int tid) {
    const float* gt = g_train + (size_t)s * (Bsz * Dsz);
    const float* gs = g_state + (size_t)s * (Bsz * Dsz);
#pragma unroll
    for (int i = 0; i < 4; i++) {
        int idx4 = tid + i * 256;          // 0..1023 float4s
        int b  = idx4 >> 6;                // 64 float4 per row
        int kc = (idx4 & 63) << 2;
        __pipeline_memcpy_async(&trb[b * TSTR + kc], &gt[idx4 * 4], 16);
        __pipeline_memcpy_async(&stb[b * TSTR + kc], &gs[idx4 * 4], 16);
    }
    __pipeline_commit();
}

__global__ void __launch_bounds__(256) ttt_kernel(const float* __restrict__ Wt,
                                                  float* __restrict__ out) {
    extern __shared__ float smem[];
    float* sm_tr    = smem;                          // [2][16*TSTR]
    float* sm_st    = smem + 2 * 16 * TSTR;          // [2][16*TSTR]
    float* sm_cross = smem + 4 * 16 * TSTR;          // [8][32]

    int tid  = threadIdx.x;
    int warp = tid >> 5;
    int lane = tid & 31;
    int r = warp >> 2;            // row within block (0,1)
    int p = warp & 3;             // k-part (0..3)
    int d1 = blockIdx.x * 2 + r;  // W row
    int k0 = p * 64 + 2 * lane;   // this lane's 2 k's

    float2 wv = *(const float2*)&Wt[d1 * Dsz + k0];

    bool rdout = (p == 0 && lane >= 16);
    int ob = lane - 16;

    stage_tile(0, sm_tr, sm_st, tid);

    for (int s = 0; s < Ssz; s++) {
        int buf = s & 1;
        float* trb = sm_tr + buf * (16 * TSTR);
        float* stb = sm_st + buf * (16 * TSTR);

        // Prefetch M row early (independent of smem pipeline)
        float4 m0, m1, m2, m3;
        if (rdout) {
            const float4* Mr = (const float4*)(g_M + ((size_t)s * Bsz + ob) * Bsz);
            m0 = Mr[0]; m1 = Mr[1]; m2 = Mr[2]; m3 = Mr[3];
        }

        if (s + 1 < Ssz) {
            stage_tile(s + 1, sm_tr + (buf ^ 1) * (16 * TSTR),
                       sm_st + (buf ^ 1) * (16 * TSTR), tid);
            __pipeline_wait_prior(1);
        } else {
            __pipeline_wait_prior(0);
        }
        __syncthreads();

        // Phase 1: partial dots over this lane's 2 k's; cache train in regs.
        float a[32];
        float2 tc[16];
#pragma unroll
        for (int b = 0; b < 16; b++) {
            float2 t  = *(const float2*)&trb[b * TSTR + k0];
            float2 sv = *(const float2*)&stb[b * TSTR + k0];
            tc[b] = t;
            a[b]      = t.x * wv.x + t.y * wv.y;      // p partial
            a[16 + b] = sv.x * wv.x + sv.y * wv.y;    // q partial
        }

        // Register-only shuffle butterfly: lane j ends with sum over lanes of a[j]
#pragma unroll
        for (int m = 16; m >= 1; m >>= 1) {
            bool up = (lane & m) != 0;
#pragma unroll
            for (int j = 0; j < m; j++) {
                float keep = up ? a[j + m] : a[j];
                float give = up ? a[j]     : a[j + m];
                a[j] = keep + __shfl_xor_sync(0xffffffffu, give, m);
            }
        }

        // Cross-warp combine (4 warps per row)
        sm_cross[warp * 32 + lane] = a[0];
        __syncthreads();
        float tot = sm_cross[(r * 4 + 0) * 32 + lane]
                  + sm_cross[(r * 4 + 1) * 32 + lane]
                  + sm_cross[(r * 4 + 2) * 32 + lane]
                  + sm_cross[(r * 4 + 3) * 32 + lane];

        // lanes 0..15: dif[b] = p[b] - state[b][d1]; lanes 16..31 hold q[b]
        float diffv = 0.0f;
        if (lane < 16) diffv = tot - stb[lane * TSTR + d1];

        float dif[16];
#pragma unroll
        for (int j = 0; j < 16; j++) dif[j] = __shfl_sync(0xffffffffu, diffv, j);

        // Readout (one warp per row): out[b][s][d1] += q[b] - lam * M[b,:].dif
        if (rdout) {
            float corr = m0.x * dif[0]  + m0.y * dif[1]  + m0.z * dif[2]  + m0.w * dif[3]
                       + m1.x * dif[4]  + m1.y * dif[5]  + m1.z * dif[6]  + m1.w * dif[7]
                       + m2.x * dif[8]  + m2.y * dif[9]  + m2.z * dif[10] + m2.w * dif[11]
                       + m3.x * dif[12] + m3.y * dif[13] + m3.z * dif[14] + m3.w * dif[15];
            float* op = out + ((size_t)ob * Ssz + s) * Dsz + d1;
            *op += tot - LAM * corr;   // ff kernel wrote g first
        }

        // Update w from register-cached train
#pragma unroll
        for (int b = 0; b < 16; b++) {
            float ld = LAM * dif[b];
            wv.x -= ld * tc[b].x;
            wv.y -= ld * tc[b].y;
        }

        __syncthreads();   // protect this step's buffers before next stage overwrites
    }
}

// ---------------------------------------------------------------------------
extern "C" void kernel_launch(void* const* d_in, const int* in_sizes, int n_in,
                              void* d_out, int out_size) {
    const float* x     = (const float*)d_in[0];
    const float* noise = (const float*)d_in[1];
    const float* a1    = (const float*)d_in[2];
    const float* a2    = (const float*)d_in[3];
    const float* Wt    = (const float*)d_in[4];
    const float* Wp    = (const float*)d_in[5];
    const float* ffa   = (const float*)d_in[6];
    const float* ffb   = (const float*)d_in[7];
    const float* ffg   = (const float*)d_in[8];
    const float* ffe   = (const float*)d_in[9];
    float* out = (float*)d_out;

    prep_kernel<<<(Bsz * Ssz * Dsz / 4) / 256, 256>>>(x, noise, a1, a2);
    prep_M_kernel<<<Ssz, 256>>>();
    ff_kernel<<<dim3((Bsz * Ssz) / 64, Dsz / 64), 256>>>(Wp, ffa, ffb, ffg, ffe, out);

    const int TTT_SMEM = (4 * 16 * TSTR + 8 * 32) * (int)sizeof(float);  // ~66 KB
    cudaFuncSetAttribute(ttt_kernel, cudaFuncAttributeMaxDynamicSharedMemorySize, TTT_SMEM);
    ttt_kernel<<<Dsz / 2, 256, TTT_SMEM>>>(Wt, out);
}

// round 10
// speedup vs baseline: 11.2392x; 2.2183x over previous
#include <cuda_runtime.h>
#include <cuda_pipeline.h>
#include <math.h>

#define Bsz 16
#define Ssz 2048
#define NP  (Ssz / 2)            // 1024 step pairs
#define Dsz 256
#define LAM (0.02f / 4096.0f)    // 0.01 * 2/(B*D)
#define TSTR 260                 // smem tile row stride (floats), padded
#define TSZ (Bsz * TSTR)         // one [16 x TSTR] tensor tile

// Scratch (device globals: allocation-free per harness rules)
__device__ float g_state[Ssz * Bsz * Dsz];   // [s][b][k]  = tanh(alpha1*x)
__device__ float g_train[Ssz * Bsz * Dsz];   // [s][b][k]  = state + noise
__device__ float g_M[Ssz * Bsz * Bsz];       // [s][b][j]  = state_s[b]·train_s[j]
__device__ float g_A[NP * Bsz * Bsz];        // [ps][b][j] = train_{s+1}[b]·train_s[j]
__device__ float g_G[NP * Bsz * Bsz];        // [ps][b][j] = state_{s+1}[b]·train_s[j]
__device__ float g_v[Bsz * Ssz * Dsz];       // [b][s][k]  = tanh(alpha2*x)

// ---------------------------------------------------------------------------
// prep: elementwise tanh/add -> state, train (as [s][b][k]) and v
// ---------------------------------------------------------------------------
__global__ void prep_kernel(const float* __restrict__ x, const float* __restrict__ noise,
                            const float* __restrict__ a1, const float* __restrict__ a2) {
    int idx4 = blockIdx.x * blockDim.x + threadIdx.x;
    int base = idx4 * 4;
    int k  = base & (Dsz - 1);
    int bs = base >> 8;
    int b  = bs >> 11;
    int s  = bs & (Ssz - 1);

    float4 xv = ((const float4*)x)[idx4];
    float4 nv = ((const float4*)noise)[idx4];
    float4 A1 = ((const float4*)a1)[k >> 2];
    float4 A2 = ((const float4*)a2)[k >> 2];

    float4 st, tr, vv;
    st.x = tanhf(A1.x * xv.x);  st.y = tanhf(A1.y * xv.y);
    st.z = tanhf(A1.z * xv.z);  st.w = tanhf(A1.w * xv.w);
    tr.x = st.x + nv.x; tr.y = st.y + nv.y; tr.z = st.z + nv.z; tr.w = st.w + nv.w;
    vv.x = tanhf(A2.x * xv.x);  vv.y = tanhf(A2.y * xv.y);
    vv.z = tanhf(A2.z * xv.z);  vv.w = tanhf(A2.w * xv.w);

    int o = (s * Bsz + b) * Dsz + k;
    *(float4*)&g_state[o] = st;
    *(float4*)&g_train[o] = tr;
    ((float4*)g_v)[idx4] = vv;
}

// ---------------------------------------------------------------------------
// prep_pair: per pair ps (s=2ps): M_s, M_{s+1}, A, G  (all 16x16)
// ---------------------------------------------------------------------------
__global__ void prep_pair_kernel() {
    extern __shared__ float sm[];
    float* s_trs = sm;
    float* s_sts = sm + TSZ;
    float* s_tr1 = sm + 2 * TSZ;
    float* s_st1 = sm + 3 * TSZ;

    int ps = blockIdx.x;
    int s  = 2 * ps;
    const float* gt = g_train + (size_t)s * (Bsz * Dsz);
    const float* gs = g_state + (size_t)s * (Bsz * Dsz);
    int tid = threadIdx.x;

#pragma unroll
    for (int i = 0; i < 4; i++) {
        int idx4 = tid + i * 256;          // 0..1023 float4s per tensor
        int b  = idx4 >> 6;
        int kc = (idx4 & 63) << 2;
        int off = b * TSTR + kc;
        *(float4*)&s_trs[off] = *(const float4*)&gt[idx4 * 4];
        *(float4*)&s_sts[off] = *(const float4*)&gs[idx4 * 4];
        *(float4*)&s_tr1[off] = *(const float4*)&gt[Bsz * Dsz + idx4 * 4];
        *(float4*)&s_st1[off] = *(const float4*)&gs[Bsz * Dsz + idx4 * 4];
    }
    __syncthreads();

    int b = tid >> 4;
    int j = tid & 15;
    float mS = 0.f, m1 = 0.f, aa = 0.f, gg = 0.f;
#pragma unroll 4
    for (int k = 0; k < Dsz; k += 4) {
        float4 tsj = *(float4*)&s_trs[j * TSTR + k];
        float4 t1j = *(float4*)&s_tr1[j * TSTR + k];
        float4 ssb = *(float4*)&s_sts[b * TSTR + k];
        float4 s1b = *(float4*)&s_st1[b * TSTR + k];
        float4 t1b = *(float4*)&s_tr1[b * TSTR + k];
        mS += ssb.x * tsj.x + ssb.y * tsj.y + ssb.z * tsj.z + ssb.w * tsj.w;
        m1 += s1b.x * t1j.x + s1b.y * t1j.y + s1b.z * t1j.z + s1b.w * t1j.w;
        aa += t1b.x * tsj.x + t1b.y * tsj.y + t1b.z * tsj.z + t1b.w * tsj.w;
        gg += s1b.x * tsj.x + s1b.y * tsj.y + s1b.z * tsj.z + s1b.w * tsj.w;
    }
    g_M[((size_t)s * Bsz + b) * Bsz + j]       = mS;
    g_M[((size_t)(s + 1) * Bsz + b) * Bsz + j] = m1;
    g_A[((size_t)ps * Bsz + b) * Bsz + j]      = aa;
    g_G[((size_t)ps * Bsz + b) * Bsz + j]      = gg;
}

// ---------------------------------------------------------------------------
// ff: out[row][j] = u(row,j) * sum_k v[row][k] * Wp[j][k]
// ---------------------------------------------------------------------------
__global__ void ff_kernel(const float* __restrict__ Wp,
                          const float* __restrict__ ffa, const float* __restrict__ ffb,
                          const float* __restrict__ ffg, const float* __restrict__ ffe,
                          float* __restrict__ out) {
    __shared__ float As[16][68];
    __shared__ float Bs[16][68];

    int rowTile = blockIdx.x * 64;
    int jTile   = blockIdx.y * 64;
    int tid = threadIdx.x;
    int tx = tid & 15;
    int ty = tid >> 4;

    float acc[4][4];
#pragma unroll
    for (int i = 0; i < 4; i++)
#pragma unroll
        for (int j = 0; j < 4; j++) acc[i][j] = 0.0f;

    int r  = tid >> 2;
    int kk = (tid & 3) * 4;

    for (int kt = 0; kt < Dsz; kt += 16) {
        float4 av = *(const float4*)&g_v[(size_t)(rowTile + r) * Dsz + kt + kk];
        float4 bv = *(const float4*)&Wp[(jTile + r) * Dsz + kt + kk];
        As[kk + 0][r] = av.x; As[kk + 1][r] = av.y; As[kk + 2][r] = av.z; As[kk + 3][r] = av.w;
        Bs[kk + 0][r] = bv.x; Bs[kk + 1][r] = bv.y; Bs[kk + 2][r] = bv.z; Bs[kk + 3][r] = bv.w;
        __syncthreads();
#pragma unroll
        for (int k2 = 0; k2 < 16; k2++) {
            float4 a = *(float4*)&As[k2][ty * 4];
            float4 b = *(float4*)&Bs[k2][tx * 4];
            acc[0][0] += a.x * b.x; acc[0][1] += a.x * b.y; acc[0][2] += a.x * b.z; acc[0][3] += a.x * b.w;
            acc[1][0] += a.y * b.x; acc[1][1] += a.y * b.y; acc[1][2] += a.y * b.z; acc[1][3] += a.y * b.w;
            acc[2][0] += a.z * b.x; acc[2][1] += a.z * b.y; acc[2][2] += a.z * b.z; acc[2][3] += a.z * b.w;
            acc[3][0] += a.w * b.x; acc[3][1] += a.w * b.y; acc[3][2] += a.w * b.z; acc[3][3] += a.w * b.w;
        }
        __syncthreads();
    }

    float gg = ffg[0];
    float ee = ffe[0];
#pragma unroll
    for (int i = 0; i < 4; i++) {
        int row = rowTile + ty * 4 + i;
#pragma unroll
        for (int j = 0; j < 4; j++) {
            int col = jTile + tx * 4 + j;
            float vv = g_v[(size_t)row * Dsz + col];
            float za = ffa[col] * vv;
            float gel = 0.5f * za * (1.0f + erff(za * 0.70710678118654752f));
            float u = gg * gel + ee * sinf(ffb[col] * vv);
            out[(size_t)row * Dsz + col] = u * acc[i][j];
        }
    }
}

// ---------------------------------------------------------------------------
// ttt: 2 rows/block, 4 warps/row, step PAIRS with precomputed A/G corrections.
// Triple-buffered cp.async staging; 2 barriers per pair; gmem prefetched
// ahead of the barrier.
// ---------------------------------------------------------------------------
__device__ __forceinline__ void stage_pair(int ps, float* dst, int tid) {
    const float* gt = g_train + (size_t)(2 * ps) * (Bsz * Dsz);
    const float* gs = g_state + (size_t)(2 * ps) * (Bsz * Dsz);
#pragma unroll
    for (int i = 0; i < 4; i++) {
        int idx4 = tid + i * 256;
        int b  = idx4 >> 6;
        int kc = (idx4 & 63) << 2;
        int off = b * TSTR + kc;
        __pipeline_memcpy_async(&dst[0 * TSZ + off], &gt[idx4 * 4], 16);
        __pipeline_memcpy_async(&dst[1 * TSZ + off], &gs[idx4 * 4], 16);
        __pipeline_memcpy_async(&dst[2 * TSZ + off], &gt[Bsz * Dsz + idx4 * 4], 16);
        __pipeline_memcpy_async(&dst[3 * TSZ + off], &gs[Bsz * Dsz + idx4 * 4], 16);
    }
    __pipeline_commit();
}

__global__ void __launch_bounds__(256, 1) ttt_kernel(const float* __restrict__ Wt,
                                                     float* __restrict__ out) {
    extern __shared__ float smem[];
    float* sm_buf   = smem;                       // [3][4*TSZ]
    float* sm_cross = smem + 3 * 4 * TSZ;         // [8 warps][2][32]

    int tid  = threadIdx.x;
    int warp = tid >> 5;
    int lane = tid & 31;
    int r = warp >> 2;             // row within block (0,1)
    int p = warp & 3;              // k-part
    int d1 = blockIdx.x * 2 + r;   // W row
    int k0 = p * 64 + 2 * lane;

    float2 wv = *(const float2*)&Wt[d1 * Dsz + k0];

    bool rdout = (p == 0 && lane >= 16);
    int  ob    = lane - 16;
    bool loA   = (lane < 16);

    stage_pair(0, sm_buf, tid);
    stage_pair(1, sm_buf + 4 * TSZ, tid);

    for (int ps = 0; ps < NP; ps++) {
        float* buf = sm_buf + (ps % 3) * (4 * TSZ);
        float* trs = buf;
        float* sts = buf + TSZ;
        float* tr1 = buf + 2 * TSZ;
        float* st1 = buf + 3 * TSZ;
        int s = 2 * ps;

        // ---- gmem prefetches (independent of smem pipeline / barrier) ----
        float4 A0, A1, A2, A3;                    // A row (lanes<16, all warps)
        if (loA) {
            const float4* Ar = (const float4*)(g_A + ((size_t)ps * Bsz + lane) * Bsz);
            A0 = Ar[0]; A1 = Ar[1]; A2 = Ar[2]; A3 = Ar[3];
        }
        float4 m0, m1, m2, m3, n0, n1, n2, n3, G0, G1, G2, G3;
        float* op0 = 0; float* op1 = 0; float o0 = 0.f, o1 = 0.f;
        if (rdout) {
            const float4* Mr = (const float4*)(g_M + ((size_t)s * Bsz + ob) * Bsz);
            m0 = Mr[0]; m1 = Mr[1]; m2 = Mr[2]; m3 = Mr[3];
            const float4* Nr = (const float4*)(g_M + ((size_t)(s + 1) * Bsz + ob) * Bsz);
            n0 = Nr[0]; n1 = Nr[1]; n2 = Nr[2]; n3 = Nr[3];
            const float4* Gr = (const float4*)(g_G + ((size_t)ps * Bsz + ob) * Bsz);
            G0 = Gr[0]; G1 = Gr[1]; G2 = Gr[2]; G3 = Gr[3];
            op0 = out + ((size_t)ob * Ssz + s) * Dsz + d1;
            op1 = op0 + Dsz;
            o0 = *op0; o1 = *op1;
        }

        __syncthreads();                           // all reads of buf(ps+2)%3 done

        if (ps + 2 < NP) {
            stage_pair(ps + 2, sm_buf + ((ps + 2) % 3) * (4 * TSZ), tid);
            __pipeline_wait_prior(2);              // buf(ps) staged
        } else {
            __pipeline_wait_prior(0);
        }

        // ---- phase 1: partial dots for BOTH steps against w0 ----
        float a[32], c[32];
        float2 tc[16];
#pragma unroll
        for (int b = 0; b < 16; b++) {
            float2 t0 = *(const float2*)&trs[b * TSTR + k0];
            float2 s0 = *(const float2*)&sts[b * TSTR + k0];
            float2 t1 = *(const float2*)&tr1[b * TSTR + k0];
            float2 s1 = *(const float2*)&st1[b * TSTR + k0];
            tc[b] = t0;
            a[b]      = t0.x * wv.x + t0.y * wv.y;   // p1 partial
            a[16 + b] = s0.x * wv.x + s0.y * wv.y;   // q1 partial
            c[b]      = t1.x * wv.x + t1.y * wv.y;   // p2_0 partial
            c[16 + b] = s1.x * wv.x + s1.y * wv.y;   // q2_0 partial
        }

        // ---- interleaved register butterfly: lane j -> sum over lanes of a[j], c[j]
#pragma unroll
        for (int m = 16; m >= 1; m >>= 1) {
            bool up = (lane & m) != 0;
#pragma unroll
            for (int j = 0; j < m; j++) {
                float ka = up ? a[j + m] : a[j];
                float ga = up ? a[j]     : a[j + m];
                a[j] = ka + __shfl_xor_sync(0xffffffffu, ga, m);
                float kc = up ? c[j + m] : c[j];
                float gc = up ? c[j]     : c[j + m];
                c[j] = kc + __shfl_xor_sync(0xffffffffu, gc, m);
            }
        }

        // ---- cross-warp combine (4 warps per row) ----
        sm_cross[(warp * 2 + 0) * 32 + lane] = a[0];
        sm_cross[(warp * 2 + 1) * 32 + lane] = c[0];
        __syncthreads();
        int rb = r * 4;
        float tot_a = sm_cross[((rb + 0) * 2) * 32 + lane]
                    + sm_cross[((rb + 1) * 2) * 32 + lane]
                    + sm_cross[((rb + 2) * 2) * 32 + lane]
                    + sm_cross[((rb + 3) * 2) * 32 + lane];
        float tot_c = sm_cross[((rb + 0) * 2 + 1) * 32 + lane]
                    + sm_cross[((rb + 1) * 2 + 1) * 32 + lane]
                    + sm_cross[((rb + 2) * 2 + 1) * 32 + lane]
                    + sm_cross[((rb + 3) * 2 + 1) * 32 + lane];

        // ---- step s: dif1 on lanes<16 (tot_a holds p1 there, q1 on lanes>=16)
        float dv1 = 0.f;
        if (loA) dv1 = tot_a - sts[lane * TSTR + d1];
        float dif1[16];
#pragma unroll
        for (int j = 0; j < 16; j++) dif1[j] = __shfl_sync(0xffffffffu, dv1, j);

        if (rdout) {
            float corr = m0.x * dif1[0]  + m0.y * dif1[1]  + m0.z * dif1[2]  + m0.w * dif1[3]
                       + m1.x * dif1[4]  + m1.y * dif1[5]  + m1.z * dif1[6]  + m1.w * dif1[7]
                       + m2.x * dif1[8]  + m2.y * dif1[9]  + m2.z * dif1[10] + m2.w * dif1[11]
                       + m3.x * dif1[12] + m3.y * dif1[13] + m3.z * dif1[14] + m3.w * dif1[15];
            *op0 = o0 + tot_a - LAM * corr;
        }

        // ---- step s+1: correct p2 with A·dif1, form dif2
        float dv2 = 0.f;
        if (loA) {
            float cA = A0.x * dif1[0]  + A0.y * dif1[1]  + A0.z * dif1[2]  + A0.w * dif1[3]
                     + A1.x * dif1[4]  + A1.y * dif1[5]  + A1.z * dif1[6]  + A1.w * dif1[7]
                     + A2.x * dif1[8]  + A2.y * dif1[9]  + A2.z * dif1[10] + A2.w * dif1[11]
                     + A3.x * dif1[12] + A3.y * dif1[13] + A3.z * dif1[14] + A3.w * dif1[15];
            dv2 = (tot_c - LAM * cA) - st1[lane * TSTR + d1];
        }
        float dif2[16];
#pragma unroll
        for (int j = 0; j < 16; j++) dif2[j] = __shfl_sync(0xffffffffu, dv2, j);

        if (rdout) {
            float cG = G0.x * dif1[0]  + G0.y * dif1[1]  + G0.z * dif1[2]  + G0.w * dif1[3]
                     + G1.x * dif1[4]  + G1.y * dif1[5]  + G1.z * dif1[6]  + G1.w * dif1[7]
                     + G2.x * dif1[8]  + G2.y * dif1[9]  + G2.z * dif1[10] + G2.w * dif1[11]
                     + G3.x * dif1[12] + G3.y * dif1[13] + G3.z * dif1[14] + G3.w * dif1[15];
            float q2 = tot_c - LAM * cG;
            float cN = n0.x * dif2[0]  + n0.y * dif2[1]  + n0.z * dif2[2]  + n0.w * dif2[3]
                     + n1.x * dif2[4]  + n1.y * dif2[5]  + n1.z * dif2[6]  + n1.w * dif2[7]
                     + n2.x * dif2[8]  + n2.y * dif2[9]  + n2.z * dif2[10] + n2.w * dif2[11]
                     + n3.x * dif2[12] + n3.y * dif2[13] + n3.z * dif2[14] + n3.w * dif2[15];
            *op1 = o1 + q2 - LAM * cN;
        }

        // ---- combined w update: w -= lam*(dif1·tr_s + dif2·tr_{s+1})
#pragma unroll
        for (int b = 0; b < 16; b++) {
            float l1 = LAM * dif1[b];
            float2 t1 = *(const float2*)&tr1[b * TSTR + k0];
            float l2 = LAM * dif2[b];
            wv.x -= l1 * tc[b].x + l2 * t1.x;
            wv.y -= l1 * tc[b].y + l2 * t1.y;
        }
    }
}

// ---------------------------------------------------------------------------
extern "C" void kernel_launch(void* const* d_in, const int* in_sizes, int n_in,
                              void* d_out, int out_size) {
    const float* x     = (const float*)d_in[0];
    const float* noise = (const float*)d_in[1];
    const float* a1    = (const float*)d_in[2];
    const float* a2    = (const float*)d_in[3];
    const float* Wt    = (const float*)d_in[4];
    const float* Wp    = (const float*)d_in[5];
    const float* ffa   = (const float*)d_in[6];
    const float* ffb   = (const float*)d_in[7];
    const float* ffg   = (const float*)d_in[8];
    const float* ffe   = (const float*)d_in[9];
    float* out = (float*)d_out;

    prep_kernel<<<(Bsz * Ssz * Dsz / 4) / 256, 256>>>(x, noise, a1, a2);

    const int PREP_SMEM = 4 * TSZ * (int)sizeof(float);               // ~66.6 KB
    cudaFuncSetAttribute(prep_pair_kernel, cudaFuncAttributeMaxDynamicSharedMemorySize, PREP_SMEM);
    prep_pair_kernel<<<NP, 256, PREP_SMEM>>>();

    ff_kernel<<<dim3((Bsz * Ssz) / 64, Dsz / 64), 256>>>(Wp, ffa, ffb, ffg, ffe, out);

    const int TTT_SMEM = (3 * 4 * TSZ + 8 * 2 * 32) * (int)sizeof(float);  // ~202 KB
    cudaFuncSetAttribute(ttt_kernel, cudaFuncAttributeMaxDynamicSharedMemorySize, TTT_SMEM);
    ttt_kernel<<<Dsz / 2, 256, TTT_SMEM>>>(Wt, out);
}